// round 12
// baseline (speedup 1.0000x reference)
#include <cuda_runtime.h>
#include <cstdint>
#include <cstddef>

// ---------------- Problem constants ----------------
#define BB 64
#define SS 2048
#define DD 6
#define HH 8
#define NCHAIN (BB*HH)      // 512 chains
#define CS 8                // steps per chunk
#define NC (SS/CS)          // 256 chunks per chain
#define SEG 16              // chunks per scan segment
#define NSEG (NC/SEG)       // 16 segments
#define NROW (BB*SS)        // 131072 rows
#define EPSN 1e-8f

// ============ Cl(4,1) ~ M4(C) via gamma matrices (constexpr tables) ========
struct CMat { int re[4][4]; int im[4][4]; };

__host__ __device__ constexpr CMat cid(){ CMat m{}; for(int r=0;r<4;r++) m.re[r][r]=1; return m; }

__host__ __device__ constexpr CMat cmul(const CMat&A, const CMat&B){
    CMat R{};
    for(int r=0;r<4;r++)for(int c=0;c<4;c++){
        int re=0, im=0;
        for(int k=0;k<4;k++){
            re += A.re[r][k]*B.re[k][c] - A.im[r][k]*B.im[k][c];
            im += A.re[r][k]*B.im[k][c] + A.im[r][k]*B.re[k][c];
        }
        R.re[r][c]=re; R.im[r][c]=im;
    }
    return R;
}

__host__ __device__ constexpr CMat gammaM(int i){
    CMat m{};
    if(i==0){ m.re[0][2]=1; m.re[1][3]=1; m.re[2][0]=1; m.re[3][1]=1; }          // sx x I
    else if(i==1){ m.im[0][2]=-1; m.im[1][3]=-1; m.im[2][0]=1; m.im[3][1]=1; }   // sy x I
    else if(i==2){ m.re[0][1]=1; m.re[1][0]=1; m.re[2][3]=-1; m.re[3][2]=-1; }   // sz x sx
    else if(i==3){ m.im[0][1]=-1; m.im[1][0]=1; m.im[2][3]=1; m.im[3][2]=-1; }   // sz x sy
    else { m.im[0][0]=1; m.im[1][1]=-1; m.im[2][2]=-1; m.im[3][3]=1; }           // i*(sz x sz)
    return m;
}

struct Tables { int col[32][4]; int pc[32][4]; int sq[32]; };
__host__ __device__ constexpr Tables build(){
    Tables t{};
    for(int A=0;A<32;A++){
        CMat M = cid();
        for(int i=0;i<5;i++) if((A>>i)&1) M = cmul(M, gammaM(i));
        for(int r=0;r<4;r++){
            for(int c=0;c<4;c++){
                if(M.re[r][c]!=0){ t.col[A][r]=c; t.pc[A][r]=(M.re[r][c]>0)?0:2; }
                else if(M.im[r][c]!=0){ t.col[A][r]=c; t.pc[A][r]=(M.im[r][c]>0)?1:3; }
            }
        }
        CMat M2 = cmul(M,M);
        t.sq[A] = M2.re[0][0];
    }
    return t;
}
__device__ constexpr Tables TB = build();

// matrix storage: float M[32]: M[r*4+c] = Re, M[16+r*4+c] = Im

// ---------------- Scratch ----------------
__device__ static float g_d [(size_t)NCHAIN * SS * 32];     // delta matrices
__device__ static float g_L [(size_t)NCHAIN * SS * 32];     // local prefix matrices (raw)
__device__ static float g_T [(size_t)NCHAIN * NC * 32];     // chunk totals (normalized)
__device__ static float g_El[(size_t)NCHAIN * NC * 32];     // segment-local exclusive prefixes
__device__ static float g_St[(size_t)NCHAIN * NSEG * 32];   // segment totals
__device__ static float g_E [(size_t)NCHAIN * NC * 32];     // per-chunk seed matrices

// ---------------- complex 4x4 matmul, D streamed from gmem -----------------
__device__ __forceinline__ void cmm_g(const float* __restrict__ Dp,
                                      const float P[32], float Q[32])
{
#pragma unroll
    for(int r=0;r<4;r++){
        const float4 drv = __ldg(reinterpret_cast<const float4*>(Dp) + r);
        const float4 div = __ldg(reinterpret_cast<const float4*>(Dp) + 4 + r);
        const float dr[4] = {drv.x, drv.y, drv.z, drv.w};
        const float di[4] = {div.x, div.y, div.z, div.w};
#pragma unroll
        for(int c=0;c<4;c++){
            float qre = 0.f, qim = 0.f;
#pragma unroll
            for(int k=0;k<4;k++){
                qre = fmaf( dr[k], P[k*4+c],    qre);
                qre = fmaf(-di[k], P[16+k*4+c], qre);
                qim = fmaf( dr[k], P[16+k*4+c], qim);
                qim = fmaf( di[k], P[k*4+c],    qim);
            }
            Q[r*4+c]    = qre;
            Q[16+r*4+c] = qim;
        }
    }
}

__device__ __forceinline__ void load32(const float* __restrict__ p, float M[32]){
#pragma unroll
    for(int q=0;q<8;q++){
        const float4 v = __ldg(reinterpret_cast<const float4*>(p) + q);
        M[4*q]=v.x; M[4*q+1]=v.y; M[4*q+2]=v.z; M[4*q+3]=v.w;
    }
}
__device__ __forceinline__ void store32(float* __restrict__ p, const float M[32], float s){
#pragma unroll
    for(int q=0;q<8;q++)
        reinterpret_cast<float4*>(p)[q] =
            make_float4(M[4*q]*s, M[4*q+1]*s, M[4*q+2]*s, M[4*q+3]*s);
}
// 1/(||x|| + eps) with ||x||^2 = Frobenius^2 / 4
__device__ __forceinline__ float mnorm_inv(const float M[32]){
    float n = 0.f;
#pragma unroll
    for(int k=0;k<32;k++) n = fmaf(M[k], M[k], n);
    return 1.0f / (sqrtf(0.25f*n) + EPSN);
}

// ======================================================================
// Kernel 0: delta -> matrix form. thread per (b,s,h).
// ======================================================================
__global__ void __launch_bounds__(256) k_delta(const float* __restrict__ x,
                                               const float* __restrict__ W_in,
                                               const float* __restrict__ b_in)
{
    __shared__ float Wt[DD*256];   // [d][k*8+h]
    __shared__ float bt[256];      // [k*8+h]

    const int tid = threadIdx.x;
    for (int i = tid; i < DD*256; i += 256){
        const int d = i >> 8, rem = i & 255, k = rem >> 3, h = rem & 7;
        Wt[i] = __ldg(W_in + d*256 + h*32 + k);
    }
    for (int i = tid; i < 256; i += 256){
        const int k = i >> 3, h = i & 7;
        bt[i] = __ldg(b_in + h*32 + k);
    }
    __syncthreads();

    const int bs = blockIdx.x * 32 + (tid >> 3);   // [0, B*S)
    const int h  = tid & 7;
    const int b  = bs >> 11;
    const int s  = bs & (SS - 1);

    const float* xp = x + (size_t)bs * DD;
    float xv[DD];
#pragma unroll
    for (int d = 0; d < DD; d++) xv[d] = __ldg(xp + d);

    float M[32];
#pragma unroll
    for (int k = 0; k < 32; k++) M[k] = 0.f;
    float n = 0.f;

#pragma unroll
    for (int A = 0; A < 32; A++){
        float u = bt[A*8 + h];
#pragma unroll
        for (int d = 0; d < DD; d++)
            u = fmaf(xv[d], Wt[d*256 + A*8 + h], u);
        if (A == 0) u += 1.0f;
        n = fmaf(u, u, n);
#pragma unroll
        for (int r = 0; r < 4; r++){
            const int c = TB.col[A][r];
            const int p = TB.pc[A][r];
            if      (p == 0) M[r*4+c]    += u;
            else if (p == 2) M[r*4+c]    -= u;
            else if (p == 1) M[16+r*4+c] += u;
            else             M[16+r*4+c] -= u;
        }
    }

    const float inv = 1.0f / (sqrtf(n) + EPSN);
    const int bh = b * HH + h;
    store32(g_d + ((size_t)bh * SS + s) * 32, M, inv);
}

// ======================================================================
// Kernel 1: chunk local prefixes. thread per (bh,c): 7 serial matmuls.
// ======================================================================
__global__ void __launch_bounds__(128) k_chunkL()
{
    const int idx = blockIdx.x * blockDim.x + threadIdx.x;   // [0, NCHAIN*NC)
    const int c  = idx & (NC - 1);
    const int bh = idx >> 8;

    const float* dbase = g_d + ((size_t)bh * SS + c * CS) * 32;
    float*       lbase = g_L + ((size_t)bh * SS + c * CS) * 32;

    float P[32], Q[32];
    load32(dbase, P);
    store32(lbase, P, 1.0f);

    for (int s = 1; s < CS; s++){
        cmm_g(dbase + s*32, P, Q);
        store32(lbase + s*32, Q, 1.0f);
#pragma unroll
        for (int k = 0; k < 32; k++) P[k] = Q[k];
    }

    const float inv = mnorm_inv(P);
    store32(g_T + ((size_t)bh * NC + c) * 32, P, inv);
}

// ======================================================================
// Kernel 2: segment-local exclusive scan. thread per (bh,seg); SEG steps.
// ======================================================================
__global__ void __launch_bounds__(128) k_scan1()
{
    const int idx = blockIdx.x * blockDim.x + threadIdx.x;   // [0, NCHAIN*NSEG)
    const int seg = idx & (NSEG - 1);
    const int bh  = idx >> 4;                                // NSEG = 16
    const int c0  = seg * SEG;

    float E[32], Q[32];
#pragma unroll
    for (int k = 0; k < 32; k++) E[k] = 0.f;
#pragma unroll
    for (int r = 0; r < 4; r++) E[r*4+r] = 1.f;              // identity

    store32(g_El + ((size_t)bh * NC + c0) * 32, E, 1.0f);

    for (int j = 0; j < SEG; j++){
        cmm_g(g_T + ((size_t)bh * NC + c0 + j) * 32, E, Q);
        const float inv = mnorm_inv(Q);
#pragma unroll
        for (int k = 0; k < 32; k++) E[k] = Q[k] * inv;
        if (j < SEG - 1)
            store32(g_El + ((size_t)bh * NC + c0 + j + 1) * 32, E, 1.0f);
        else
            store32(g_St + ((size_t)bh * NSEG + seg) * 32, E, 1.0f);
    }
}

// ======================================================================
// Kernel 3: seeds. thread per (bh,c): walk segment totals (redundant,
// latency-hidden) then E = N(El * G).
// ======================================================================
__global__ void __launch_bounds__(128) k_seed()
{
    const int idx = blockIdx.x * blockDim.x + threadIdx.x;   // [0, NCHAIN*NC)
    const int c  = idx & (NC - 1);
    const int bh = idx >> 8;
    const int seg = c / SEG;

    float G[32], Q[32];
#pragma unroll
    for (int k = 0; k < 32; k++) G[k] = 0.f;
#pragma unroll
    for (int r = 0; r < 4; r++) G[r*4+r] = 1.f;

    for (int j = 0; j < seg; j++){                           // G = St_{seg-1} ... St_0
        cmm_g(g_St + ((size_t)bh * NSEG + j) * 32, G, Q);
        const float inv = mnorm_inv(Q);
#pragma unroll
        for (int k = 0; k < 32; k++) G[k] = Q[k] * inv;
    }

    float R[32];
    cmm_g(g_El + ((size_t)bh * NC + c) * 32, G, R);          // El left, G right

    const float inv = mnorm_inv(R);
    store32(g_E + ((size_t)bh * NC + c) * 32, R, inv);
}

// ======================================================================
// Kernel 4: FUSED psi + projection. thread per (b,t).
// For each head: Q = L * E ; psi = invT(Q)/||psi|| accumulated into out proj.
// NOTE: invT produces 4*x_A (trace formula, kappa = tr(I) = 4), so the
// per-head scale is 0.25 * mnorm_inv(Q). Getting this wrong leaves psi
// scaled 4x, which corrupts the bias-relative weighting in the output
// normalize (the exact 4.01e-2 failure of R8-R11).
// ======================================================================
__global__ void __launch_bounds__(128, 4) k_fuse(const float* __restrict__ W_out,
                                                 const float* __restrict__ b_out,
                                                 float* __restrict__ out)
{
    __shared__ float Wsm[256 * 32];
    __shared__ float bsm[32];

    const int tid = threadIdx.x;
    for (int i = tid; i < 256 * 32 / 4; i += 128)
        reinterpret_cast<float4*>(Wsm)[i] = __ldg(reinterpret_cast<const float4*>(W_out) + i);
    if (tid < 8)
        reinterpret_cast<float4*>(bsm)[tid] = __ldg(reinterpret_cast<const float4*>(b_out) + tid);
    __syncthreads();

    const int r = blockIdx.x * 128 + tid;                    // r = b*SS + t
    const int b = r >> 11;
    const int t = r & (SS - 1);
    const int c = t >> 3;                                    // CS = 8

    float acc[32];
#pragma unroll
    for (int j = 0; j < 32; j++) acc[j] = 0.f;

#pragma unroll
    for (int h = 0; h < HH; h++){
        const int bh = b * HH + h;

        float E[32], Q[32];
        load32(g_E + ((size_t)bh * NC + c) * 32, E);
        cmm_g(g_L + ((size_t)bh * SS + t) * 32, E, Q);       // L left, E right

        // psi norm via Frobenius; FOLD IN the 1/4 for the kappa=4 of invT
        const float inv = 0.25f * mnorm_inv(Q);

#pragma unroll
        for (int A = 0; A < 32; A++){
            float v = 0.f;
#pragma unroll
            for (int rr = 0; rr < 4; rr++){
                const int cc = TB.col[A][rr];
                const int p  = TB.pc[A][rr];
                const float e = (p==0 || p==2) ? Q[cc*4+rr] : Q[16+cc*4+rr];
                const int pos = ((p==0 || p==3) ? 1 : -1) * TB.sq[A];
                v = (pos > 0) ? (v + e) : (v - e);
            }
            v *= inv;                                        // normalized psi component
            const int row = h*32 + A;
#pragma unroll
            for (int q = 0; q < 8; q++){
                const float4 w = *reinterpret_cast<const float4*>(&Wsm[row*32 + q*4]);
                acc[q*4+0] = fmaf(v, w.x, acc[q*4+0]);
                acc[q*4+1] = fmaf(v, w.y, acc[q*4+1]);
                acc[q*4+2] = fmaf(v, w.z, acc[q*4+2]);
                acc[q*4+3] = fmaf(v, w.w, acc[q*4+3]);
            }
        }
    }

#pragma unroll
    for (int j = 0; j < 32; j++) acc[j] += bsm[j];

    float n = 0.f;
#pragma unroll
    for (int j = 0; j < 32; j++) n = fmaf(acc[j], acc[j], n);
    const float inv = 1.0f / (sqrtf(n) + EPSN);

    float4* op = reinterpret_cast<float4*>(out + (size_t)r * 32);
#pragma unroll
    for (int q = 0; q < 8; q++)
        op[q] = make_float4(acc[4*q]*inv, acc[4*q+1]*inv, acc[4*q+2]*inv, acc[4*q+3]*inv);
}

// ======================================================================
extern "C" void kernel_launch(void* const* d_in, const int* in_sizes, int n_in,
                              void* d_out, int out_size)
{
    const float* x     = (const float*)d_in[0];
    const float* W_in  = (const float*)d_in[1];
    const float* b_in  = (const float*)d_in[2];
    const float* W_out = (const float*)d_in[3];
    const float* b_out = (const float*)d_in[4];
    float* out = (float*)d_out;

    k_delta <<<(BB*SS*HH)/256, 256>>>(x, W_in, b_in);   // 4096 blocks
    k_chunkL<<<(NCHAIN*NC)/128, 128>>>();               // 1024 blocks
    k_scan1 <<<(NCHAIN*NSEG)/128, 128>>>();             // 64 blocks
    k_seed  <<<(NCHAIN*NC)/128, 128>>>();               // 1024 blocks
    k_fuse  <<<NROW/128, 128>>>(W_out, b_out, out);     // 1024 blocks
}

// round 13
// speedup vs baseline: 1.2600x; 1.2600x over previous
#include <cuda_runtime.h>
#include <cstdint>
#include <cstddef>

// ---------------- Problem constants ----------------
#define BB 64
#define SS 2048
#define DD 6
#define HH 8
#define NCHAIN (BB*HH)      // 512 chains
#define CS 8                // steps per chunk
#define NC (SS/CS)          // 256 chunks per chain
#define SEG 16              // chunks per scan segment
#define NSEG (NC/SEG)       // 16 segments
#define NROW (BB*SS)        // 131072 rows
#define EPSN 1e-8f

// ============ Cl(4,1) ~ M4(C) via gamma matrices (constexpr tables) ========
struct CMat { int re[4][4]; int im[4][4]; };

__host__ __device__ constexpr CMat cid(){ CMat m{}; for(int r=0;r<4;r++) m.re[r][r]=1; return m; }

__host__ __device__ constexpr CMat cmul(const CMat&A, const CMat&B){
    CMat R{};
    for(int r=0;r<4;r++)for(int c=0;c<4;c++){
        int re=0, im=0;
        for(int k=0;k<4;k++){
            re += A.re[r][k]*B.re[k][c] - A.im[r][k]*B.im[k][c];
            im += A.re[r][k]*B.im[k][c] + A.im[r][k]*B.re[k][c];
        }
        R.re[r][c]=re; R.im[r][c]=im;
    }
    return R;
}

__host__ __device__ constexpr CMat gammaM(int i){
    CMat m{};
    if(i==0){ m.re[0][2]=1; m.re[1][3]=1; m.re[2][0]=1; m.re[3][1]=1; }          // sx x I
    else if(i==1){ m.im[0][2]=-1; m.im[1][3]=-1; m.im[2][0]=1; m.im[3][1]=1; }   // sy x I
    else if(i==2){ m.re[0][1]=1; m.re[1][0]=1; m.re[2][3]=-1; m.re[3][2]=-1; }   // sz x sx
    else if(i==3){ m.im[0][1]=-1; m.im[1][0]=1; m.im[2][3]=1; m.im[3][2]=-1; }   // sz x sy
    else { m.im[0][0]=1; m.im[1][1]=-1; m.im[2][2]=-1; m.im[3][3]=1; }           // i*(sz x sz)
    return m;
}

// col[A][r]: nonzero column of Gamma_A in row r; pc: 0:+1 1:+i 2:-1 3:-i; sq: Gamma_A^2
// fA/fS: forward  — matrix entry e = sum_k fS[e][k] * u[fA[e][k]]
// iA/iS: inverse  — Wtil[e][j]     = sum_k iS[e][k] * W_out[iA[e][k]][j]   (tc_A = 4 x_A)
struct Tables {
    int col[32][4]; int pc[32][4]; int sq[32];
    int fA[32][4]; int fS[32][4];
    int iA[32][4]; int iS[32][4];
};
__host__ __device__ constexpr Tables build(){
    Tables t{};
    for(int A=0;A<32;A++){
        CMat M = cid();
        for(int i=0;i<5;i++) if((A>>i)&1) M = cmul(M, gammaM(i));
        for(int r=0;r<4;r++){
            for(int c=0;c<4;c++){
                if(M.re[r][c]!=0){ t.col[A][r]=c; t.pc[A][r]=(M.re[r][c]>0)?0:2; }
                else if(M.im[r][c]!=0){ t.col[A][r]=c; t.pc[A][r]=(M.im[r][c]>0)?1:3; }
            }
        }
        CMat M2 = cmul(M,M);
        t.sq[A] = M2.re[0][0];
    }
    int fcnt[32] = {}, icnt[32] = {};
    for(int A=0;A<32;A++){
        for(int rr=0;rr<4;rr++){
            const int cc = t.col[A][rr];
            const int p  = t.pc[A][rr];
            const int im = (p==1 || p==3) ? 1 : 0;
            // forward: M[rr][cc] (re or im) += (p<2 ? +1 : -1) * u_A
            const int ef = im*16 + rr*4 + cc;
            t.fA[ef][fcnt[ef]] = A;
            t.fS[ef][fcnt[ef]] = (p==0 || p==1) ? 1 : -1;
            fcnt[ef]++;
            // inverse: tc_A += pos * Q[cc][rr] (re or im), pos = ((p==0||p==3)?1:-1)*sq
            const int ei = im*16 + cc*4 + rr;
            t.iA[ei][icnt[ei]] = A;
            t.iS[ei][icnt[ei]] = ((p==0 || p==3) ? 1 : -1) * t.sq[A];
            icnt[ei]++;
        }
    }
    return t;
}
__device__ constexpr Tables TB = build();

// matrix storage: float M[32]: M[r*4+c] = Re, M[16+r*4+c] = Im

// ---------------- Scratch ----------------
__device__ static float g_L [(size_t)NCHAIN * SS * 32];     // local prefix matrices (raw)
__device__ static float g_T [(size_t)NCHAIN * NC * 32];     // chunk totals (normalized)
__device__ static float g_El[(size_t)NCHAIN * NC * 32];     // segment-local exclusive prefixes
__device__ static float g_St[(size_t)NCHAIN * NSEG * 32];   // segment totals
__device__ static float g_G [(size_t)NCHAIN * NSEG * 32];   // segment exclusive prefixes
__device__ static float g_E [(size_t)NCHAIN * NC * 32];     // per-chunk seed matrices

// ---------------- complex 4x4 matmul, D streamed from gmem -----------------
__device__ __forceinline__ void cmm_g(const float* __restrict__ Dp,
                                      const float P[32], float Q[32])
{
#pragma unroll
    for(int r=0;r<4;r++){
        const float4 drv = __ldg(reinterpret_cast<const float4*>(Dp) + r);
        const float4 div = __ldg(reinterpret_cast<const float4*>(Dp) + 4 + r);
        const float dr[4] = {drv.x, drv.y, drv.z, drv.w};
        const float di[4] = {div.x, div.y, div.z, div.w};
#pragma unroll
        for(int c=0;c<4;c++){
            float qre = 0.f, qim = 0.f;
#pragma unroll
            for(int k=0;k<4;k++){
                qre = fmaf( dr[k], P[k*4+c],    qre);
                qre = fmaf(-di[k], P[16+k*4+c], qre);
                qim = fmaf( dr[k], P[16+k*4+c], qim);
                qim = fmaf( di[k], P[k*4+c],    qim);
            }
            Q[r*4+c]    = qre;
            Q[16+r*4+c] = qim;
        }
    }
}

// ---------------- complex 4x4 matmul, D in smem column layout Ms[e*128+tid] -
__device__ __forceinline__ void cmm_s(const float* __restrict__ Ms, int tid,
                                      const float P[32], float Q[32])
{
#pragma unroll
    for(int r=0;r<4;r++){
        float dr[4], di[4];
#pragma unroll
        for(int k=0;k<4;k++){
            dr[k] = Ms[(r*4+k)*128 + tid];
            di[k] = Ms[(16+r*4+k)*128 + tid];
        }
#pragma unroll
        for(int c=0;c<4;c++){
            float qre = 0.f, qim = 0.f;
#pragma unroll
            for(int k=0;k<4;k++){
                qre = fmaf( dr[k], P[k*4+c],    qre);
                qre = fmaf(-di[k], P[16+k*4+c], qre);
                qim = fmaf( dr[k], P[16+k*4+c], qim);
                qim = fmaf( di[k], P[k*4+c],    qim);
            }
            Q[r*4+c]    = qre;
            Q[16+r*4+c] = qim;
        }
    }
}

__device__ __forceinline__ void load32(const float* __restrict__ p, float M[32]){
#pragma unroll
    for(int q=0;q<8;q++){
        const float4 v = __ldg(reinterpret_cast<const float4*>(p) + q);
        M[4*q]=v.x; M[4*q+1]=v.y; M[4*q+2]=v.z; M[4*q+3]=v.w;
    }
}
__device__ __forceinline__ void store32(float* __restrict__ p, const float M[32], float s){
#pragma unroll
    for(int q=0;q<8;q++)
        reinterpret_cast<float4*>(p)[q] =
            make_float4(M[4*q]*s, M[4*q+1]*s, M[4*q+2]*s, M[4*q+3]*s);
}
// 1/(||x|| + eps) with ||x||^2 = Frobenius^2 / 4
__device__ __forceinline__ float mnorm_inv(const float M[32]){
    float n = 0.f;
#pragma unroll
    for(int k=0;k<32;k++) n = fmaf(M[k], M[k], n);
    return 1.0f / (sqrtf(0.25f*n) + EPSN);
}

// ======================================================================
// Kernel 0 (FUSED delta+chunk): thread per (bh,c). Builds the 8 raw delta
// matrices in-place (NO per-delta normalization — scaling commutes; totals
// are normalized) and chains them. Delta matrix staged via a conflict-free
// smem column so live registers stay ~75 (u[32]+P vs P+Q, never all three).
// ======================================================================
__global__ void __launch_bounds__(128) k_chunkF(const float* __restrict__ x,
                                                const float* __restrict__ W_in,
                                                const float* __restrict__ b_in)
{
    __shared__ float Wt[DD*256];     // W_in as-is: [d*256 + h*32 + A]
    __shared__ float bt[256];
    __shared__ float Msm[32*128];    // entry-major columns: Msm[e*128 + tid]

    const int tid = threadIdx.x;
    for (int i = tid; i < DD*256; i += 128) Wt[i] = __ldg(W_in + i);
    for (int i = tid; i < 256;    i += 128) bt[i] = __ldg(b_in + i);
    __syncthreads();

    const int idx = blockIdx.x * 128 + tid;      // [0, NCHAIN*NC)
    const int c  = idx & (NC - 1);
    const int bh = idx >> 8;
    const int b  = bh >> 3;
    const int h  = bh & 7;

    const float* xb = x + ((size_t)b * SS + c * CS) * DD;
    float*    lbase = g_L + ((size_t)bh * SS + c * CS) * 32;

    float P[32], Q[32];

#pragma unroll
    for (int s = 0; s < CS; s++){
        // x for this step (24B-aligned)
        float xv[DD];
        {
            const float2* xp2 = reinterpret_cast<const float2*>(xb + s*DD);
            const float2 v0 = __ldg(xp2), v1 = __ldg(xp2+1), v2 = __ldg(xp2+2);
            xv[0]=v0.x; xv[1]=v0.y; xv[2]=v1.x; xv[3]=v1.y; xv[4]=v2.x; xv[5]=v2.y;
        }
        // u_A = b + x@W  (+1 on scalar blade); raw, unnormalized
        float u[32];
#pragma unroll
        for (int A = 0; A < 32; A++){
            float uu = bt[h*32 + A];
#pragma unroll
            for (int d = 0; d < DD; d++)
                uu = fmaf(xv[d], Wt[d*256 + h*32 + A], uu);
            u[A] = uu;
        }
        u[0] += 1.0f;

        if (s == 0){
            // P = M(u) built directly in registers (u dead after)
#pragma unroll
            for (int e = 0; e < 32; e++){
                float v = 0.f;
#pragma unroll
                for (int k = 0; k < 4; k++)
                    v = (TB.fS[e][k] > 0) ? (v + u[TB.fA[e][k]]) : (v - u[TB.fA[e][k]]);
                P[e] = v;
            }
            store32(lbase, P, 1.0f);
        } else {
            // stage M(u) into own smem column (no cross-thread sharing, no sync)
#pragma unroll
            for (int e = 0; e < 32; e++){
                float v = 0.f;
#pragma unroll
                for (int k = 0; k < 4; k++)
                    v = (TB.fS[e][k] > 0) ? (v + u[TB.fA[e][k]]) : (v - u[TB.fA[e][k]]);
                Msm[e*128 + tid] = v;
            }
            cmm_s(Msm, tid, P, Q);
            store32(lbase + s*32, Q, 1.0f);
#pragma unroll
            for (int k = 0; k < 32; k++) P[k] = Q[k];
        }
    }

    const float inv = mnorm_inv(P);
    store32(g_T + ((size_t)bh * NC + c) * 32, P, inv);
}

// ======================================================================
// Kernel 1: segment-local exclusive scan. thread per (bh,seg); SEG steps.
// ======================================================================
__global__ void __launch_bounds__(128) k_scan1()
{
    const int idx = blockIdx.x * blockDim.x + threadIdx.x;   // [0, NCHAIN*NSEG)
    const int seg = idx & (NSEG - 1);
    const int bh  = idx >> 4;                                // NSEG = 16
    const int c0  = seg * SEG;

    float E[32], Q[32];
#pragma unroll
    for (int k = 0; k < 32; k++) E[k] = 0.f;
#pragma unroll
    for (int r = 0; r < 4; r++) E[r*4+r] = 1.f;              // identity

    store32(g_El + ((size_t)bh * NC + c0) * 32, E, 1.0f);

    for (int j = 0; j < SEG; j++){
        cmm_g(g_T + ((size_t)bh * NC + c0 + j) * 32, E, Q);
        const float inv = mnorm_inv(Q);
#pragma unroll
        for (int k = 0; k < 32; k++) E[k] = Q[k] * inv;
        if (j < SEG - 1)
            store32(g_El + ((size_t)bh * NC + c0 + j + 1) * 32, E, 1.0f);
        else
            store32(g_St + ((size_t)bh * NSEG + seg) * 32, E, 1.0f);
    }
}

// ======================================================================
// Kernel 2: segment exclusive prefixes. thread per (bh,seg): redundant
// walk of <= NSEG-1 segment totals (8192 threads, fully parallel).
// ======================================================================
__global__ void __launch_bounds__(128) k_scan2g()
{
    const int idx = blockIdx.x * blockDim.x + threadIdx.x;   // [0, NCHAIN*NSEG)
    const int seg = idx & (NSEG - 1);
    const int bh  = idx >> 4;

    float G[32], Q[32];
#pragma unroll
    for (int k = 0; k < 32; k++) G[k] = 0.f;
#pragma unroll
    for (int r = 0; r < 4; r++) G[r*4+r] = 1.f;

    for (int j = 0; j < seg; j++){                           // G_seg = St_{seg-1}...St_0
        cmm_g(g_St + ((size_t)bh * NSEG + j) * 32, G, Q);
        const float inv = mnorm_inv(Q);
#pragma unroll
        for (int k = 0; k < 32; k++) G[k] = Q[k] * inv;
    }

    store32(g_G + ((size_t)bh * NSEG + seg) * 32, G, 1.0f);
}

// ======================================================================
// Kernel 3: seeds. thread per (bh,c): E = N(El * G). Single combine.
// ======================================================================
__global__ void __launch_bounds__(128) k_seed()
{
    const int idx = blockIdx.x * blockDim.x + threadIdx.x;   // [0, NCHAIN*NC)
    const int c  = idx & (NC - 1);
    const int bh = idx >> 8;
    const int seg = c / SEG;

    float G[32], R[32];
    load32(g_G + ((size_t)bh * NSEG + seg) * 32, G);
    cmm_g(g_El + ((size_t)bh * NC + c) * 32, G, R);          // El left, G right

    const float inv = mnorm_inv(R);
    store32(g_E + ((size_t)bh * NC + c) * 32, R, inv);
}

// ======================================================================
// Kernel 4: FUSED psi + projection. thread per (b,t).
// W pre-transformed to Q-entry domain: Wtil[(h*32+e)*32+j] =
//   0.25 * sum_k iS[e][k] * W_out[(h*32+iA[e][k])*32 + j]
// (0.25 folds the kappa=4 of the trace inverse transform — see R11.)
// Main loop: acc_j += (Q[e] * inv) * Wtil[...]   — no gather, no tc array.
// ======================================================================
__global__ void __launch_bounds__(128, 4) k_fuse(const float* __restrict__ W_out,
                                                 const float* __restrict__ b_out,
                                                 float* __restrict__ out)
{
    __shared__ float Wsm[256 * 32];   // [(h*32+e)*32 + j]
    __shared__ float bsm[32];

    const int tid = threadIdx.x;
    for (int i = tid; i < 256 * 32; i += 128){
        const int j  = i & 31;
        const int he = i >> 5;
        const int e  = he & 31;
        const int h  = he >> 5;
        float w = 0.f;
#pragma unroll
        for (int k = 0; k < 4; k++){
            const float ww = __ldg(W_out + ((size_t)(h*32 + TB.iA[e][k]))*32 + j);
            w = (TB.iS[e][k] > 0) ? (w + ww) : (w - ww);
        }
        Wsm[i] = 0.25f * w;
    }
    if (tid < 8)
        reinterpret_cast<float4*>(bsm)[tid] = __ldg(reinterpret_cast<const float4*>(b_out) + tid);
    __syncthreads();

    const int r = blockIdx.x * 128 + tid;                    // r = b*SS + t
    const int b = r >> 11;
    const int t = r & (SS - 1);
    const int c = t >> 3;                                    // CS = 8

    float acc[32];
#pragma unroll
    for (int j = 0; j < 32; j++) acc[j] = 0.f;

#pragma unroll
    for (int h = 0; h < HH; h++){
        const int bh = b * HH + h;

        float E[32], Q[32];
        load32(g_E + ((size_t)bh * NC + c) * 32, E);
        cmm_g(g_L + ((size_t)bh * SS + t) * 32, E, Q);       // L left, E right

        const float inv = mnorm_inv(Q);                      // 1/||psi|| (0.25 in Wsm)

#pragma unroll
        for (int e = 0; e < 32; e++){
            const float v = Q[e] * inv;
            const float* wr = &Wsm[(h*32 + e)*32];
#pragma unroll
            for (int q = 0; q < 8; q++){
                const float4 w = *reinterpret_cast<const float4*>(wr + q*4);
                acc[q*4+0] = fmaf(v, w.x, acc[q*4+0]);
                acc[q*4+1] = fmaf(v, w.y, acc[q*4+1]);
                acc[q*4+2] = fmaf(v, w.z, acc[q*4+2]);
                acc[q*4+3] = fmaf(v, w.w, acc[q*4+3]);
            }
        }
    }

#pragma unroll
    for (int j = 0; j < 32; j++) acc[j] += bsm[j];

    float n = 0.f;
#pragma unroll
    for (int j = 0; j < 32; j++) n = fmaf(acc[j], acc[j], n);
    const float inv = 1.0f / (sqrtf(n) + EPSN);

    float4* op = reinterpret_cast<float4*>(out + (size_t)r * 32);
#pragma unroll
    for (int q = 0; q < 8; q++)
        op[q] = make_float4(acc[4*q]*inv, acc[4*q+1]*inv, acc[4*q+2]*inv, acc[4*q+3]*inv);
}

// ======================================================================
extern "C" void kernel_launch(void* const* d_in, const int* in_sizes, int n_in,
                              void* d_out, int out_size)
{
    const float* x     = (const float*)d_in[0];
    const float* W_in  = (const float*)d_in[1];
    const float* b_in  = (const float*)d_in[2];
    const float* W_out = (const float*)d_in[3];
    const float* b_out = (const float*)d_in[4];
    float* out = (float*)d_out;

    k_chunkF<<<(NCHAIN*NC)/128, 128>>>(x, W_in, b_in);  // 1024 blocks (delta+chunk fused)
    k_scan1 <<<(NCHAIN*NSEG)/128, 128>>>();             // 64 blocks
    k_scan2g<<<(NCHAIN*NSEG)/128, 128>>>();             // 64 blocks
    k_seed  <<<(NCHAIN*NC)/128, 128>>>();               // 1024 blocks
    k_fuse  <<<NROW/128, 128>>>(W_out, b_out, out);     // 1024 blocks
}

// round 14
// speedup vs baseline: 1.3009x; 1.0325x over previous
#include <cuda_runtime.h>
#include <cstdint>
#include <cstddef>

// ---------------- Problem constants ----------------
#define BB 64
#define SS 2048
#define DD 6
#define HH 8
#define NCHAIN (BB*HH)      // 512 chains
#define CS 4                // steps per chunk
#define NC (SS/CS)          // 512 chunks per chain
#define SEG 16              // chunks per scan segment
#define NSEG (NC/SEG)       // 32 segments
#define NROW (BB*SS)        // 131072 rows
#define EPSN 1e-8f

// ============ Cl(4,1) ~ M4(C) via gamma matrices (constexpr tables) ========
struct CMat { int re[4][4]; int im[4][4]; };

__host__ __device__ constexpr CMat cid(){ CMat m{}; for(int r=0;r<4;r++) m.re[r][r]=1; return m; }

__host__ __device__ constexpr CMat cmul(const CMat&A, const CMat&B){
    CMat R{};
    for(int r=0;r<4;r++)for(int c=0;c<4;c++){
        int re=0, im=0;
        for(int k=0;k<4;k++){
            re += A.re[r][k]*B.re[k][c] - A.im[r][k]*B.im[k][c];
            im += A.re[r][k]*B.im[k][c] + A.im[r][k]*B.re[k][c];
        }
        R.re[r][c]=re; R.im[r][c]=im;
    }
    return R;
}

__host__ __device__ constexpr CMat gammaM(int i){
    CMat m{};
    if(i==0){ m.re[0][2]=1; m.re[1][3]=1; m.re[2][0]=1; m.re[3][1]=1; }          // sx x I
    else if(i==1){ m.im[0][2]=-1; m.im[1][3]=-1; m.im[2][0]=1; m.im[3][1]=1; }   // sy x I
    else if(i==2){ m.re[0][1]=1; m.re[1][0]=1; m.re[2][3]=-1; m.re[3][2]=-1; }   // sz x sx
    else if(i==3){ m.im[0][1]=-1; m.im[1][0]=1; m.im[2][3]=1; m.im[3][2]=-1; }   // sz x sy
    else { m.im[0][0]=1; m.im[1][1]=-1; m.im[2][2]=-1; m.im[3][3]=1; }           // i*(sz x sz)
    return m;
}

// fA/fS: forward  — matrix entry e = sum_k fS[e][k] * u[fA[e][k]]
// iA/iS: inverse  — Wtil[e][j]     = sum_k iS[e][k] * W_out[iA[e][k]][j]   (tc_A = 4 x_A)
struct Tables {
    int col[32][4]; int pc[32][4]; int sq[32];
    int fA[32][4]; int fS[32][4];
    int iA[32][4]; int iS[32][4];
};
__host__ __device__ constexpr Tables build(){
    Tables t{};
    for(int A=0;A<32;A++){
        CMat M = cid();
        for(int i=0;i<5;i++) if((A>>i)&1) M = cmul(M, gammaM(i));
        for(int r=0;r<4;r++){
            for(int c=0;c<4;c++){
                if(M.re[r][c]!=0){ t.col[A][r]=c; t.pc[A][r]=(M.re[r][c]>0)?0:2; }
                else if(M.im[r][c]!=0){ t.col[A][r]=c; t.pc[A][r]=(M.im[r][c]>0)?1:3; }
            }
        }
        CMat M2 = cmul(M,M);
        t.sq[A] = M2.re[0][0];
    }
    int fcnt[32] = {}, icnt[32] = {};
    for(int A=0;A<32;A++){
        for(int rr=0;rr<4;rr++){
            const int cc = t.col[A][rr];
            const int p  = t.pc[A][rr];
            const int im = (p==1 || p==3) ? 1 : 0;
            const int ef = im*16 + rr*4 + cc;
            t.fA[ef][fcnt[ef]] = A;
            t.fS[ef][fcnt[ef]] = (p==0 || p==1) ? 1 : -1;
            fcnt[ef]++;
            const int ei = im*16 + cc*4 + rr;
            t.iA[ei][icnt[ei]] = A;
            t.iS[ei][icnt[ei]] = ((p==0 || p==3) ? 1 : -1) * t.sq[A];
            icnt[ei]++;
        }
    }
    return t;
}
__device__ constexpr Tables TB = build();

// matrix storage: float M[32]: M[r*4+c] = Re, M[16+r*4+c] = Im

// ---------------- Scratch ----------------
__device__ static float g_L [(size_t)NCHAIN * SS * 32];     // local prefix matrices (raw)
__device__ static float g_T [(size_t)NCHAIN * NC * 32];     // chunk totals (normalized)
__device__ static float g_El[(size_t)NCHAIN * NC * 32];     // segment-local exclusive prefixes
__device__ static float g_St[(size_t)NCHAIN * NSEG * 32];   // segment totals
__device__ static float g_G [(size_t)NCHAIN * NSEG * 32];   // segment exclusive prefixes
__device__ static float g_E [(size_t)NCHAIN * NC * 32];     // per-chunk seed matrices

// ---------------- complex 4x4 matmul, D streamed from gmem -----------------
__device__ __forceinline__ void cmm_g(const float* __restrict__ Dp,
                                      const float P[32], float Q[32])
{
#pragma unroll
    for(int r=0;r<4;r++){
        const float4 drv = __ldg(reinterpret_cast<const float4*>(Dp) + r);
        const float4 div = __ldg(reinterpret_cast<const float4*>(Dp) + 4 + r);
        const float dr[4] = {drv.x, drv.y, drv.z, drv.w};
        const float di[4] = {div.x, div.y, div.z, div.w};
#pragma unroll
        for(int c=0;c<4;c++){
            float qre = 0.f, qim = 0.f;
#pragma unroll
            for(int k=0;k<4;k++){
                qre = fmaf( dr[k], P[k*4+c],    qre);
                qre = fmaf(-di[k], P[16+k*4+c], qre);
                qim = fmaf( dr[k], P[16+k*4+c], qim);
                qim = fmaf( di[k], P[k*4+c],    qim);
            }
            Q[r*4+c]    = qre;
            Q[16+r*4+c] = qim;
        }
    }
}

// ---------------- complex 4x4 matmul, D in smem column layout Ms[e*128+tid] -
__device__ __forceinline__ void cmm_s(const float* __restrict__ Ms, int tid,
                                      const float P[32], float Q[32])
{
#pragma unroll
    for(int r=0;r<4;r++){
        float dr[4], di[4];
#pragma unroll
        for(int k=0;k<4;k++){
            dr[k] = Ms[(r*4+k)*128 + tid];
            di[k] = Ms[(16+r*4+k)*128 + tid];
        }
#pragma unroll
        for(int c=0;c<4;c++){
            float qre = 0.f, qim = 0.f;
#pragma unroll
            for(int k=0;k<4;k++){
                qre = fmaf( dr[k], P[k*4+c],    qre);
                qre = fmaf(-di[k], P[16+k*4+c], qre);
                qim = fmaf( dr[k], P[16+k*4+c], qim);
                qim = fmaf( di[k], P[k*4+c],    qim);
            }
            Q[r*4+c]    = qre;
            Q[16+r*4+c] = qim;
        }
    }
}

__device__ __forceinline__ void load32(const float* __restrict__ p, float M[32]){
#pragma unroll
    for(int q=0;q<8;q++){
        const float4 v = __ldg(reinterpret_cast<const float4*>(p) + q);
        M[4*q]=v.x; M[4*q+1]=v.y; M[4*q+2]=v.z; M[4*q+3]=v.w;
    }
}
__device__ __forceinline__ void store32(float* __restrict__ p, const float M[32], float s){
#pragma unroll
    for(int q=0;q<8;q++)
        reinterpret_cast<float4*>(p)[q] =
            make_float4(M[4*q]*s, M[4*q+1]*s, M[4*q+2]*s, M[4*q+3]*s);
}
// 1/(||x|| + eps) with ||x||^2 = Frobenius^2 / 4
__device__ __forceinline__ float mnorm_inv(const float M[32]){
    float n = 0.f;
#pragma unroll
    for(int k=0;k<32;k++) n = fmaf(M[k], M[k], n);
    return 1.0f / (sqrtf(0.25f*n) + EPSN);
}

// ======================================================================
// Kernel 0 (FUSED delta+chunk): thread per (bh,c), CS=4 steps. Raw deltas
// (no per-delta normalization; scaling commutes, totals normalized).
// Delta matrix staged via conflict-free smem column to cap live registers.
// ======================================================================
__global__ void __launch_bounds__(128) k_chunkF(const float* __restrict__ x,
                                                const float* __restrict__ W_in,
                                                const float* __restrict__ b_in)
{
    __shared__ float Wt[DD*256];     // W_in as-is: [d*256 + h*32 + A]
    __shared__ float bt[256];
    __shared__ float Msm[32*128];    // entry-major columns: Msm[e*128 + tid]

    const int tid = threadIdx.x;
    for (int i = tid; i < DD*256; i += 128) Wt[i] = __ldg(W_in + i);
    for (int i = tid; i < 256;    i += 128) bt[i] = __ldg(b_in + i);
    __syncthreads();

    const int idx = blockIdx.x * 128 + tid;      // [0, NCHAIN*NC)
    const int c  = idx & (NC - 1);               // NC = 512
    const int bh = idx >> 9;
    const int b  = bh >> 3;
    const int h  = bh & 7;

    const float* xb = x + ((size_t)b * SS + c * CS) * DD;
    float*    lbase = g_L + ((size_t)bh * SS + c * CS) * 32;

    float P[32], Q[32];

#pragma unroll
    for (int s = 0; s < CS; s++){
        float xv[DD];
        {
            const float2* xp2 = reinterpret_cast<const float2*>(xb + s*DD);
            const float2 v0 = __ldg(xp2), v1 = __ldg(xp2+1), v2 = __ldg(xp2+2);
            xv[0]=v0.x; xv[1]=v0.y; xv[2]=v1.x; xv[3]=v1.y; xv[4]=v2.x; xv[5]=v2.y;
        }
        float u[32];
#pragma unroll
        for (int A = 0; A < 32; A++){
            float uu = bt[h*32 + A];
#pragma unroll
            for (int d = 0; d < DD; d++)
                uu = fmaf(xv[d], Wt[d*256 + h*32 + A], uu);
            u[A] = uu;
        }
        u[0] += 1.0f;

        if (s == 0){
#pragma unroll
            for (int e = 0; e < 32; e++){
                float v = 0.f;
#pragma unroll
                for (int k = 0; k < 4; k++)
                    v = (TB.fS[e][k] > 0) ? (v + u[TB.fA[e][k]]) : (v - u[TB.fA[e][k]]);
                P[e] = v;
            }
            store32(lbase, P, 1.0f);
        } else {
#pragma unroll
            for (int e = 0; e < 32; e++){
                float v = 0.f;
#pragma unroll
                for (int k = 0; k < 4; k++)
                    v = (TB.fS[e][k] > 0) ? (v + u[TB.fA[e][k]]) : (v - u[TB.fA[e][k]]);
                Msm[e*128 + tid] = v;
            }
            cmm_s(Msm, tid, P, Q);
            store32(lbase + s*32, Q, 1.0f);
#pragma unroll
            for (int k = 0; k < 32; k++) P[k] = Q[k];
        }
    }

    const float inv = mnorm_inv(P);
    store32(g_T + ((size_t)bh * NC + c) * 32, P, inv);
}

// ======================================================================
// Kernel 1: segment-local exclusive scan. thread per (bh,seg); SEG steps.
// ======================================================================
__global__ void __launch_bounds__(128) k_scan1()
{
    const int idx = blockIdx.x * blockDim.x + threadIdx.x;   // [0, NCHAIN*NSEG)
    const int seg = idx & (NSEG - 1);                        // NSEG = 32
    const int bh  = idx >> 5;
    const int c0  = seg * SEG;

    float E[32], Q[32];
#pragma unroll
    for (int k = 0; k < 32; k++) E[k] = 0.f;
#pragma unroll
    for (int r = 0; r < 4; r++) E[r*4+r] = 1.f;              // identity

    store32(g_El + ((size_t)bh * NC + c0) * 32, E, 1.0f);

    for (int j = 0; j < SEG; j++){
        cmm_g(g_T + ((size_t)bh * NC + c0 + j) * 32, E, Q);
        const float inv = mnorm_inv(Q);
#pragma unroll
        for (int k = 0; k < 32; k++) E[k] = Q[k] * inv;
        if (j < SEG - 1)
            store32(g_El + ((size_t)bh * NC + c0 + j + 1) * 32, E, 1.0f);
        else
            store32(g_St + ((size_t)bh * NSEG + seg) * 32, E, 1.0f);
    }
}

// ======================================================================
// Kernel 2: segment exclusive prefixes. thread per (bh,seg): redundant
// walk of <= NSEG-1 segment totals (16384 threads, fully parallel).
// ======================================================================
__global__ void __launch_bounds__(128) k_scan2g()
{
    const int idx = blockIdx.x * blockDim.x + threadIdx.x;   // [0, NCHAIN*NSEG)
    const int seg = idx & (NSEG - 1);
    const int bh  = idx >> 5;

    float G[32], Q[32];
#pragma unroll
    for (int k = 0; k < 32; k++) G[k] = 0.f;
#pragma unroll
    for (int r = 0; r < 4; r++) G[r*4+r] = 1.f;

    for (int j = 0; j < seg; j++){                           // G_seg = St_{seg-1}...St_0
        cmm_g(g_St + ((size_t)bh * NSEG + j) * 32, G, Q);
        const float inv = mnorm_inv(Q);
#pragma unroll
        for (int k = 0; k < 32; k++) G[k] = Q[k] * inv;
    }

    store32(g_G + ((size_t)bh * NSEG + seg) * 32, G, 1.0f);
}

// ======================================================================
// Kernel 3: seeds. thread per (bh,c): E = N(El * G). Single combine.
// ======================================================================
__global__ void __launch_bounds__(128) k_seed()
{
    const int idx = blockIdx.x * blockDim.x + threadIdx.x;   // [0, NCHAIN*NC)
    const int c  = idx & (NC - 1);
    const int bh = idx >> 9;
    const int seg = c >> 4;                                  // SEG = 16

    float G[32], R[32];
    load32(g_G + ((size_t)bh * NSEG + seg) * 32, G);
    cmm_g(g_El + ((size_t)bh * NC + c) * 32, G, R);          // El left, G right

    const float inv = mnorm_inv(R);
    store32(g_E + ((size_t)bh * NC + c) * 32, R, inv);
}

// ======================================================================
// Kernel 4: FUSED psi + projection, HEAD-SPLIT. 2 threads per output row
// (paired as lanes xor 16 within a warp), 4 heads each, shfl reduction.
// Wsm holds the 0.25-scaled entry-domain W (kappa=4 of trace inverse).
// ======================================================================
__global__ void __launch_bounds__(128, 4) k_fuse(const float* __restrict__ W_out,
                                                 const float* __restrict__ b_out,
                                                 float* __restrict__ out)
{
    __shared__ float Wsm[256 * 32];   // [(h*32+e)*32 + j]
    __shared__ float bsm[32];

    const int tid = threadIdx.x;
    for (int i = tid; i < 256 * 32; i += 128){
        const int j  = i & 31;
        const int he = i >> 5;
        const int e  = he & 31;
        const int h  = he >> 5;
        float w = 0.f;
#pragma unroll
        for (int k = 0; k < 4; k++){
            const float ww = __ldg(W_out + ((size_t)(h*32 + TB.iA[e][k]))*32 + j);
            w = (TB.iS[e][k] > 0) ? (w + ww) : (w - ww);
        }
        Wsm[i] = 0.25f * w;
    }
    if (tid < 8)
        reinterpret_cast<float4*>(bsm)[tid] = __ldg(reinterpret_cast<const float4*>(b_out) + tid);
    __syncthreads();

    const int lane = tid & 31;
    const int wid  = tid >> 5;
    const int half = lane >> 4;                              // 0 or 1: heads 0-3 / 4-7
    const int rloc = wid * 16 + (lane & 15);                 // 0..63
    const int r = blockIdx.x * 64 + rloc;                    // r = b*SS + t
    const int b = r >> 11;
    const int t = r & (SS - 1);
    const int c = t >> 2;                                    // CS = 4

    float acc[32];
#pragma unroll
    for (int j = 0; j < 32; j++) acc[j] = 0.f;

#pragma unroll
    for (int hh = 0; hh < 4; hh++){
        const int h  = half * 4 + hh;
        const int bh = b * HH + h;

        float E[32], Q[32];
        load32(g_E + ((size_t)bh * NC + c) * 32, E);
        cmm_g(g_L + ((size_t)bh * SS + t) * 32, E, Q);       // L left, E right

        const float inv = mnorm_inv(Q);                      // 1/||psi|| (0.25 in Wsm)

#pragma unroll
        for (int e = 0; e < 32; e++){
            const float v = Q[e] * inv;
            const float* wr = &Wsm[(h*32 + e)*32];
#pragma unroll
            for (int q = 0; q < 8; q++){
                const float4 w = *reinterpret_cast<const float4*>(wr + q*4);
                acc[q*4+0] = fmaf(v, w.x, acc[q*4+0]);
                acc[q*4+1] = fmaf(v, w.y, acc[q*4+1]);
                acc[q*4+2] = fmaf(v, w.z, acc[q*4+2]);
                acc[q*4+3] = fmaf(v, w.w, acc[q*4+3]);
            }
        }
    }

    // combine the two head-halves (lanes xor 16)
#pragma unroll
    for (int j = 0; j < 32; j++)
        acc[j] += __shfl_xor_sync(0xffffffffu, acc[j], 16);

    if (half == 0){
#pragma unroll
        for (int j = 0; j < 32; j++) acc[j] += bsm[j];

        float n = 0.f;
#pragma unroll
        for (int j = 0; j < 32; j++) n = fmaf(acc[j], acc[j], n);
        const float inv = 1.0f / (sqrtf(n) + EPSN);

        float4* op = reinterpret_cast<float4*>(out + (size_t)r * 32);
#pragma unroll
        for (int q = 0; q < 8; q++)
            op[q] = make_float4(acc[4*q]*inv, acc[4*q+1]*inv, acc[4*q+2]*inv, acc[4*q+3]*inv);
    }
}

// ======================================================================
extern "C" void kernel_launch(void* const* d_in, const int* in_sizes, int n_in,
                              void* d_out, int out_size)
{
    const float* x     = (const float*)d_in[0];
    const float* W_in  = (const float*)d_in[1];
    const float* b_in  = (const float*)d_in[2];
    const float* W_out = (const float*)d_in[3];
    const float* b_out = (const float*)d_in[4];
    float* out = (float*)d_out;

    k_chunkF<<<(NCHAIN*NC)/128, 128>>>(x, W_in, b_in);  // 2048 blocks (delta+chunk fused)
    k_scan1 <<<(NCHAIN*NSEG)/128, 128>>>();             // 128 blocks
    k_scan2g<<<(NCHAIN*NSEG)/128, 128>>>();             // 128 blocks
    k_seed  <<<(NCHAIN*NC)/128, 128>>>();               // 2048 blocks
    k_fuse  <<<NROW/64, 128>>>(W_out, b_out, out);      // 2048 blocks
}